// round 1
// baseline (speedup 1.0000x reference)
#include <cuda_runtime.h>
#include <math.h>

#define BOUND 10.0f
#define EPSF  1e-6f
#define MIN_SCALE 1e-4f

#define MAXD 1024
#define MAXK 64

// Precomputed spline tables (scratch; allocation-free per harness rules)
__device__ float g_xk[MAXD * (MAXK + 1)];
__device__ float g_yk[MAXD * (MAXK + 1)];
__device__ float g_sl[MAXD * (MAXK + 1)];
__device__ float g_scale[MAXD];

__device__ __forceinline__ float softplusf(float x) {
    // log1p(exp(x)) with overflow guard (matches jax.nn.softplus to fp32 tol)
    return (x > 20.0f) ? x : log1pf(__expf(x));
}

// One block per dim d, K threads. Computes knots xk/yk (softmax*2B -> cumsum),
// softplus slopes, and output scale.
__global__ void spline_preproc_kernel(const float* __restrict__ raw_w,
                                      const float* __restrict__ raw_h,
                                      const float* __restrict__ raw_s,
                                      const float* __restrict__ log_scale,
                                      int D, int K) {
    const int d = blockIdx.x;
    const int t = threadIdx.x;      // 0..K-1
    __shared__ float red[MAXK];
    __shared__ float cum[MAXK + 1];

    // ---------- widths -> xk ----------
    {
        float x = raw_w[d * K + t];
        red[t] = x; __syncthreads();
        for (int s = K >> 1; s > 0; s >>= 1) {
            if (t < s) red[t] = fmaxf(red[t], red[t + s]);
            __syncthreads();
        }
        float m = red[0]; __syncthreads();
        float e = __expf(x - m);
        red[t] = e; __syncthreads();
        for (int s = K >> 1; s > 0; s >>= 1) {
            if (t < s) red[t] += red[t + s];
            __syncthreads();
        }
        float sum = red[0]; __syncthreads();
        float w = e * (2.0f * BOUND) / sum;
        red[t] = w; __syncthreads();
        if (t == 0) {                       // sequential cumsum = jnp.cumsum order
            float acc = -BOUND;
            cum[0] = acc;
            for (int k = 0; k < K; k++) { acc += red[k]; cum[k + 1] = acc; }
        }
        __syncthreads();
        g_xk[d * (K + 1) + t] = cum[t];
        if (t == 0) g_xk[d * (K + 1) + K] = cum[K];
        __syncthreads();
    }

    // ---------- heights -> yk ----------
    {
        float x = raw_h[d * K + t];
        red[t] = x; __syncthreads();
        for (int s = K >> 1; s > 0; s >>= 1) {
            if (t < s) red[t] = fmaxf(red[t], red[t + s]);
            __syncthreads();
        }
        float m = red[0]; __syncthreads();
        float e = __expf(x - m);
        red[t] = e; __syncthreads();
        for (int s = K >> 1; s > 0; s >>= 1) {
            if (t < s) red[t] += red[t + s];
            __syncthreads();
        }
        float sum = red[0]; __syncthreads();
        float h = e * (2.0f * BOUND) / sum;
        red[t] = h; __syncthreads();
        if (t == 0) {
            float acc = -BOUND;
            cum[0] = acc;
            for (int k = 0; k < K; k++) { acc += red[k]; cum[k + 1] = acc; }
        }
        __syncthreads();
        g_yk[d * (K + 1) + t] = cum[t];
        if (t == 0) g_yk[d * (K + 1) + K] = cum[K];
    }

    // ---------- slopes (softplus) ----------
    g_sl[d * (K + 1) + t] = softplusf(raw_s[d * (K + 1) + t]);
    if (t == 0) {
        g_sl[d * (K + 1) + K] = softplusf(raw_s[d * (K + 1) + K]);
        g_scale[d] = softplusf(log_scale[d]) + MIN_SCALE;
    }
}

// Main kernel: each block covers DTILE=32 dims x ROWS rows.
// Lane (tid&31) = dim offset -> coalesced 128B u/out accesses.
// Knot tables staged in shared (per-dim stride K+1=65, odd -> good bank spread).
#define DTILE 32
#define ROWS  256
#define TPB   256

__global__ void rqs_main_kernel(const float* __restrict__ u,
                                const float* __restrict__ tau,
                                const float* __restrict__ bias,
                                float* __restrict__ out,
                                int B, int D, int K) {
    extern __shared__ float sh[];
    const int Kp1 = K + 1;
    float* sxk = sh;                       // DTILE * Kp1
    float* syk = sxk + DTILE * Kp1;
    float* ssl = syk + DTILE * Kp1;
    float* sscale = ssl + DTILE * Kp1;     // DTILE
    float* sbias  = sscale + DTILE;        // DTILE

    const int d0 = blockIdx.x * DTILE;
    const int ntab = DTILE * Kp1;
    for (int i = threadIdx.x; i < ntab; i += TPB) {
        sxk[i] = g_xk[d0 * Kp1 + i];
        syk[i] = g_yk[d0 * Kp1 + i];
        ssl[i] = g_sl[d0 * Kp1 + i];
    }
    if (threadIdx.x < DTILE) {
        sscale[threadIdx.x] = g_scale[d0 + threadIdx.x];
        sbias[threadIdx.x]  = bias[d0 + threadIdx.x];
    }
    __syncthreads();

    const int lane = threadIdx.x & (DTILE - 1);
    const int rgrp = threadIdx.x / DTILE;          // 0..7
    const int d = d0 + lane;
    const float* xk = sxk + lane * Kp1;
    const float* yk = syk + lane * Kp1;
    const float* sl = ssl + lane * Kp1;
    const float scale = sscale[lane];
    const float bi = sbias[lane];

    const int row0 = blockIdx.y * ROWS;
    const int rowEnd = min(row0 + ROWS, B);

    for (int r = row0 + rgrp; r < rowEnd; r += TPB / DTILE) {
        const float uu = u[(long)r * D + d];
        const float tv = tau[r];
        const float us = fminf(fmaxf(uu, EPSF), 1.0f - EPSF);
        const float z = __logf(us) - log1pf(-us);

        float res;
        if (z > -BOUND && z < BOUND) {
            // largest idx in [0, K-1] with xk[idx] <= z  (== searchsorted right - 1)
            int idx = 0;
            #pragma unroll
            for (int st = 32; st > 0; st >>= 1) {
                int c = idx + st;
                if (c <= K - 1 && xk[c] <= z) idx = c;
            }
            const float x0 = xk[idx];
            const float w  = xk[idx + 1] - x0;   // exact: cumsum step
            const float y0 = yk[idx];
            const float h  = yk[idx + 1] - y0;
            const float dk0 = sl[idx];
            const float dk1 = sl[idx + 1];
            const float theta = __fdividef(z - x0, w);
            const float s = __fdividef(h, w);
            const float t1m = theta * (1.0f - theta);
            const float den = s + (dk0 + dk1 - 2.0f * s) * t1m;
            res = y0 + h * __fdividef(s * theta * theta + dk0 * t1m, den);
        } else {
            res = z;
        }
        out[(long)r * D + d] = tv * (res * scale + bi);
    }
}

extern "C" void kernel_launch(void* const* d_in, const int* in_sizes, int n_in,
                              void* d_out, int out_size) {
    const float* u         = (const float*)d_in[0];
    const float* tau       = (const float*)d_in[1];
    const float* log_scale = (const float*)d_in[2];
    const float* bias      = (const float*)d_in[3];
    const float* raw_w     = (const float*)d_in[4];
    const float* raw_h     = (const float*)d_in[5];
    const float* raw_s     = (const float*)d_in[6];
    float* out = (float*)d_out;

    const int D = in_sizes[2];
    const int B = in_sizes[0] / D;
    const int K = in_sizes[4] / D;

    // 1) Precompute spline tables (depends only on params, but must run each
    //    launch for determinism; it's tiny).
    spline_preproc_kernel<<<D, K>>>(raw_w, raw_h, raw_s, log_scale, D, K);

    // 2) Main transform
    dim3 grid(D / DTILE, (B + ROWS - 1) / ROWS);
    size_t shbytes = (size_t)(3 * DTILE * (K + 1) + 2 * DTILE) * sizeof(float);
    rqs_main_kernel<<<grid, TPB, shbytes>>>(u, tau, bias, out, B, D, K);
}

// round 2
// speedup vs baseline: 1.2282x; 1.2282x over previous
#include <cuda_runtime.h>
#include <math.h>

#define BOUND 10.0f
#define EPSF  1e-6f
#define MIN_SCALE 1e-4f

#define MAXD 1024
#define K64  64
#define CELLS 256
#define CELLS_PER_UNIT (256.0f / 20.0f)   // 12.8

// Precomputed packed spline tables (scratch; allocation-free per harness rules)
__device__ float4 g_P0[MAXD * K64];       // {x0, 1/w, y0, h}
__device__ float2 g_P1[MAXD * K64];       // {d0, d0 + d1 - 2*s}
__device__ unsigned int g_tab[MAXD * (CELLS / 4)];  // 4 packed u8 lower-bound idx per cell
__device__ float g_scale[MAXD];

__device__ __forceinline__ float softplusf(float x) {
    return (x > 20.0f) ? x : log1pf(__expf(x));
}

// One block per dim, 64 threads. softmax -> scan -> knots -> packed params + cell table.
__global__ void spline_preproc_kernel(const float* __restrict__ raw_w,
                                      const float* __restrict__ raw_h,
                                      const float* __restrict__ raw_s,
                                      const float* __restrict__ log_scale) {
    const int d = blockIdx.x;
    const int t = threadIdx.x;          // 0..63
    const int lane = t & 31, wid = t >> 5;

    __shared__ float sxk[K64 + 1], syk[K64 + 1], ssl[K64 + 1];
    __shared__ float sred[K64];
    __shared__ float s2[4];

    // ---- widths softmax ----
    float xw = raw_w[d * K64 + t];
    float m = xw;
    #pragma unroll
    for (int off = 16; off > 0; off >>= 1) m = fmaxf(m, __shfl_xor_sync(0xffffffff, m, off));
    if (lane == 0) s2[wid] = m;
    __syncthreads();
    m = fmaxf(s2[0], s2[1]);
    float ew = __expf(xw - m);
    float sm = ew;
    #pragma unroll
    for (int off = 16; off > 0; off >>= 1) sm += __shfl_xor_sync(0xffffffff, sm, off);
    if (lane == 0) s2[2 + wid] = sm;
    __syncthreads();
    float wsum = s2[2] + s2[3];
    float ww = ew * (2.0f * BOUND) / wsum;

    // inclusive scan of widths
    float v = ww;
    #pragma unroll
    for (int off = 1; off < K64; off <<= 1) {
        sred[t] = v; __syncthreads();
        if (t >= off) v += sred[t - off];
        __syncthreads();
    }
    sxk[t + 1] = v - BOUND;
    if (t == 0) sxk[0] = -BOUND;
    __syncthreads();

    // ---- heights softmax ----
    float xh = raw_h[d * K64 + t];
    float mh = xh;
    #pragma unroll
    for (int off = 16; off > 0; off >>= 1) mh = fmaxf(mh, __shfl_xor_sync(0xffffffff, mh, off));
    if (lane == 0) s2[wid] = mh;
    __syncthreads();
    mh = fmaxf(s2[0], s2[1]);
    float eh = __expf(xh - mh);
    float sh2 = eh;
    #pragma unroll
    for (int off = 16; off > 0; off >>= 1) sh2 += __shfl_xor_sync(0xffffffff, sh2, off);
    if (lane == 0) s2[2 + wid] = sh2;
    __syncthreads();
    float hsum = s2[2] + s2[3];
    float hh = eh * (2.0f * BOUND) / hsum;

    float vh = hh;
    #pragma unroll
    for (int off = 1; off < K64; off <<= 1) {
        sred[t] = vh; __syncthreads();
        if (t >= off) vh += sred[t - off];
        __syncthreads();
    }
    syk[t + 1] = vh - BOUND;
    if (t == 0) syk[0] = -BOUND;

    // ---- slopes ----
    ssl[t] = softplusf(raw_s[d * (K64 + 1) + t]);
    if (t == 0) {
        ssl[K64] = softplusf(raw_s[d * (K64 + 1) + K64]);
        g_scale[d] = softplusf(log_scale[d]) + MIN_SCALE;
    }
    __syncthreads();

    // ---- pack per-interval params ----
    {
        float x0 = sxk[t], y0 = syk[t];
        float inv_w = 1.0f / ww;
        float s = hh / ww;
        float dk0 = ssl[t], dk1 = ssl[t + 1];
        g_P0[d * K64 + t] = make_float4(x0, inv_w, y0, hh);
        g_P1[d * K64 + t] = make_float2(dk0, dk0 + dk1 - 2.0f * s);
    }

    // ---- cell table: lower-bound interval index for each cell's left edge ----
    {
        unsigned int packed = 0;
        #pragma unroll
        for (int j = 0; j < 4; j++) {
            int c = t * 4 + j;
            float left = -BOUND + (float)c * (20.0f / (float)CELLS);
            int idx = 0;
            #pragma unroll
            for (int st = 32; st > 0; st >>= 1) {
                int cand = idx + st;
                if (cand <= K64 - 1 && sxk[cand] <= left) idx = cand;
            }
            packed |= ((unsigned int)idx) << (8 * j);
        }
        g_tab[d * (CELLS / 4) + t] = packed;
    }
}

// Main kernel: DTILE=16 dims per block, 256 threads (16 row-groups).
#define DTILE 16
#define TPB   256

__global__ void __launch_bounds__(TPB)
rqs_main_kernel(const float* __restrict__ u,
                const float* __restrict__ tau,
                const float* __restrict__ bias,
                float* __restrict__ out,
                int B, int D) {
    __shared__ float4 sP0[DTILE * K64];          // 16 KB
    __shared__ float2 sP1[DTILE * K64];          // 8 KB
    __shared__ unsigned char sTab[DTILE * CELLS];// 4 KB
    __shared__ float sScale[DTILE], sBias[DTILE];

    const int d0 = blockIdx.x * DTILE;

    for (int i = threadIdx.x; i < DTILE * K64; i += TPB) {
        sP0[i] = g_P0[d0 * K64 + i];
        sP1[i] = g_P1[d0 * K64 + i];
    }
    for (int i = threadIdx.x; i < DTILE * (CELLS / 4); i += TPB) {
        ((unsigned int*)sTab)[i] = g_tab[d0 * (CELLS / 4) + i];
    }
    if (threadIdx.x < DTILE) {
        sScale[threadIdx.x] = g_scale[d0 + threadIdx.x];
        sBias[threadIdx.x]  = bias[d0 + threadIdx.x];
    }
    __syncthreads();

    const int lane = threadIdx.x & (DTILE - 1);
    const int rgrp = threadIdx.x / DTILE;            // 0..15
    const int d = d0 + lane;

    const float4* __restrict__ P0l = sP0 + lane * K64;
    const float2* __restrict__ P1l = sP1 + lane * K64;
    const float*  __restrict__ xs  = (const float*)P0l;   // x0 at stride-4 floats
    const unsigned char* __restrict__ tab = sTab + lane * CELLS;
    const float scale = sScale[lane];
    const float bi = sBias[lane];

    const int rstride = gridDim.y * (TPB / DTILE);

    for (int r = blockIdx.y * (TPB / DTILE) + rgrp; r < B; r += rstride) {
        const float uu = u[(long)r * D + d];
        const float tv = tau[r];
        const float us = fminf(fmaxf(uu, EPSF), 1.0f - EPSF);
        const float om = 1.0f - us;                      // exact for us>=0.5 (Sterbenz)
        const float z = __logf(__fdividef(us, om));

        float res;
        if (z > -BOUND && z < BOUND) {
            int c = (int)((z + BOUND) * CELLS_PER_UNIT);
            c = max(0, min(CELLS - 1, c));
            int idx = tab[c];
            int nxt = idx + 1;
            while (nxt < K64 && xs[4 * nxt] <= z) { idx = nxt; ++nxt; }

            const float4 p = P0l[idx];                   // {x0, 1/w, y0, h}
            const float2 q = P1l[idx];                   // {d0, d0+d1-2s}
            const float theta = (z - p.x) * p.y;
            const float t1m = theta * (1.0f - theta);
            const float s = p.w * p.y;                   // h/w
            const float den = fmaf(q.y, t1m, s);
            const float num = fmaf(s * theta, theta, q.x * t1m);
            res = fmaf(p.w, __fdividef(num, den), p.z);
        } else {
            res = z;
        }
        out[(long)r * D + d] = tv * fmaf(res, scale, bi);
    }
}

extern "C" void kernel_launch(void* const* d_in, const int* in_sizes, int n_in,
                              void* d_out, int out_size) {
    const float* u         = (const float*)d_in[0];
    const float* tau       = (const float*)d_in[1];
    const float* log_scale = (const float*)d_in[2];
    const float* bias      = (const float*)d_in[3];
    const float* raw_w     = (const float*)d_in[4];
    const float* raw_h     = (const float*)d_in[5];
    const float* raw_s     = (const float*)d_in[6];
    float* out = (float*)d_out;

    const int D = in_sizes[2];
    const int B = in_sizes[0] / D;

    spline_preproc_kernel<<<D, K64>>>(raw_w, raw_h, raw_s, log_scale);

    dim3 grid(D / DTILE, 16);
    rqs_main_kernel<<<grid, TPB>>>(u, tau, bias, out, B, D);
}

// round 6
// speedup vs baseline: 1.2965x; 1.0556x over previous
#include <cuda_runtime.h>
#include <math.h>

#define BOUND 10.0f
#define EPSF  1e-6f
#define MIN_SCALE 1e-4f

#define MAXD 1024
#define K64  64
#define CELLS 256
#define CELLS_PER_UNIT (256.0f / 20.0f)   // 12.8

// Precomputed packed spline tables (scratch; allocation-free per harness rules)
__device__ float4 g_P0[MAXD * K64];       // {x0, 1/w, y0, h}
__device__ float2 g_P1[MAXD * K64];       // {d0, d0 + d1 - 2*s}
__device__ unsigned int g_tab[MAXD * (CELLS / 4)];  // 4 packed u8 lower-bound idx per cell
__device__ float g_scale[MAXD];

__device__ __forceinline__ float softplusf(float x) {
    return (x > 20.0f) ? x : log1pf(__expf(x));
}

// One block per dim, 64 threads. softmax -> scan -> knots -> packed params + cell table.
__global__ void spline_preproc_kernel(const float* __restrict__ raw_w,
                                      const float* __restrict__ raw_h,
                                      const float* __restrict__ raw_s,
                                      const float* __restrict__ log_scale) {
    const int d = blockIdx.x;
    const int t = threadIdx.x;          // 0..63
    const int lane = t & 31, wid = t >> 5;

    __shared__ float sxk[K64 + 1], syk[K64 + 1], ssl[K64 + 1];
    __shared__ float sred[K64];
    __shared__ float s2[4];

    // ---- widths softmax ----
    float xw = raw_w[d * K64 + t];
    float m = xw;
    #pragma unroll
    for (int off = 16; off > 0; off >>= 1) m = fmaxf(m, __shfl_xor_sync(0xffffffff, m, off));
    if (lane == 0) s2[wid] = m;
    __syncthreads();
    m = fmaxf(s2[0], s2[1]);
    float ew = __expf(xw - m);
    float sm = ew;
    #pragma unroll
    for (int off = 16; off > 0; off >>= 1) sm += __shfl_xor_sync(0xffffffff, sm, off);
    if (lane == 0) s2[2 + wid] = sm;
    __syncthreads();
    float wsum = s2[2] + s2[3];
    float ww = ew * (2.0f * BOUND) / wsum;

    // inclusive scan of widths
    float v = ww;
    #pragma unroll
    for (int off = 1; off < K64; off <<= 1) {
        sred[t] = v; __syncthreads();
        if (t >= off) v += sred[t - off];
        __syncthreads();
    }
    sxk[t + 1] = v - BOUND;
    if (t == 0) sxk[0] = -BOUND;
    __syncthreads();

    // ---- heights softmax ----
    float xh = raw_h[d * K64 + t];
    float mh = xh;
    #pragma unroll
    for (int off = 16; off > 0; off >>= 1) mh = fmaxf(mh, __shfl_xor_sync(0xffffffff, mh, off));
    if (lane == 0) s2[wid] = mh;
    __syncthreads();
    mh = fmaxf(s2[0], s2[1]);
    float eh = __expf(xh - mh);
    float sh2 = eh;
    #pragma unroll
    for (int off = 16; off > 0; off >>= 1) sh2 += __shfl_xor_sync(0xffffffff, sh2, off);
    if (lane == 0) s2[2 + wid] = sh2;
    __syncthreads();
    float hsum = s2[2] + s2[3];
    float hh = eh * (2.0f * BOUND) / hsum;

    float vh = hh;
    #pragma unroll
    for (int off = 1; off < K64; off <<= 1) {
        sred[t] = vh; __syncthreads();
        if (t >= off) vh += sred[t - off];
        __syncthreads();
    }
    syk[t + 1] = vh - BOUND;
    if (t == 0) syk[0] = -BOUND;

    // ---- slopes ----
    ssl[t] = softplusf(raw_s[d * (K64 + 1) + t]);
    if (t == 0) {
        ssl[K64] = softplusf(raw_s[d * (K64 + 1) + K64]);
        g_scale[d] = softplusf(log_scale[d]) + MIN_SCALE;
    }
    __syncthreads();

    // ---- pack per-interval params ----
    {
        float x0 = sxk[t], y0 = syk[t];
        float inv_w = 1.0f / ww;
        float s = hh / ww;
        float dk0 = ssl[t], dk1 = ssl[t + 1];
        g_P0[d * K64 + t] = make_float4(x0, inv_w, y0, hh);
        g_P1[d * K64 + t] = make_float2(dk0, dk0 + dk1 - 2.0f * s);
    }

    // ---- cell table: lower-bound interval index for each cell's left edge ----
    {
        unsigned int packed = 0;
        #pragma unroll
        for (int j = 0; j < 4; j++) {
            int c = t * 4 + j;
            float left = -BOUND + (float)c * (20.0f / (float)CELLS);
            int idx = 0;
            #pragma unroll
            for (int st = 32; st > 0; st >>= 1) {
                int cand = idx + st;
                if (cand <= K64 - 1 && sxk[cand] <= left) idx = cand;
            }
            packed |= ((unsigned int)idx) << (8 * j);
        }
        g_tab[d * (CELLS / 4) + t] = packed;
    }
}

// Main kernel: DTILE=16 dims per block, 256 threads (16 row-groups).
// All per-lane smem strides padded to 65 entries so `lane` rotates banks:
//   sXK probe: bank=(lane+nxt)%32  -> conflict-free for distinct lanes
//   sTab:      bank=(lane + c/4)%32
//   sP0/sP1:   4/2-word groups rotated by lane
#define DTILE 16
#define TPB   256
#define STRD  65           // padded per-dim stride (entries)
#define TABSTRD 260        // padded tab stride (bytes) = 65 words

__global__ void __launch_bounds__(TPB)
rqs_main_kernel(const float* __restrict__ u,
                const float* __restrict__ tau,
                const float* __restrict__ bias,
                float* __restrict__ out,
                int B, int D) {
    __shared__ float4 sP0[DTILE * STRD];            // 16640 B
    __shared__ float2 sP1[DTILE * STRD];            //  8320 B
    __shared__ float  sXK[DTILE * STRD];            //  4160 B
    __shared__ unsigned char sTab[DTILE * TABSTRD]; //  4160 B
    __shared__ float sScale[DTILE], sBias[DTILE];

    const int d0 = blockIdx.x * DTILE;

    for (int i = threadIdx.x; i < DTILE * K64; i += TPB) {
        const int dim = i >> 6, k = i & 63;
        const float4 p = g_P0[d0 * K64 + i];
        sP0[dim * STRD + k] = p;
        sXK[dim * STRD + k] = p.x;
        sP1[dim * STRD + k] = g_P1[d0 * K64 + i];
    }
    for (int i = threadIdx.x; i < DTILE * (CELLS / 4); i += TPB) {
        const int dim = i >> 6, j = i & 63;
        *(unsigned int*)(sTab + dim * TABSTRD + 4 * j) = g_tab[d0 * (CELLS / 4) + i];
    }
    if (threadIdx.x < DTILE) {
        sScale[threadIdx.x] = g_scale[d0 + threadIdx.x];
        sBias[threadIdx.x]  = bias[d0 + threadIdx.x];
    }
    __syncthreads();

    const int lane = threadIdx.x & (DTILE - 1);
    const int rgrp = threadIdx.x / DTILE;            // 0..15
    const int d = d0 + lane;

    const float4* __restrict__ P0l = sP0 + lane * STRD;
    const float2* __restrict__ P1l = sP1 + lane * STRD;
    const float*  __restrict__ xs  = sXK + lane * STRD;
    const unsigned char* __restrict__ tab = sTab + lane * TABSTRD;
    const float scale = sScale[lane];
    const float bi = sBias[lane];

    const int rstride = gridDim.y * (TPB / DTILE);

    for (int r = blockIdx.y * (TPB / DTILE) + rgrp; r < B; r += rstride) {
        const float uu = u[(long)r * D + d];
        const float tv = tau[r];
        const float us = fminf(fmaxf(uu, EPSF), 1.0f - EPSF);
        const float om = 1.0f - us;                      // exact for us>=0.5 (Sterbenz)
        const float z = __logf(__fdividef(us, om));

        float res;
        if (z > -BOUND && z < BOUND) {
            int c = (int)((z + BOUND) * CELLS_PER_UNIT);
            c = max(0, min(CELLS - 1, c));
            int idx = tab[c];
            int nxt = idx + 1;
            while (nxt < K64 && xs[nxt] <= z) { idx = nxt; ++nxt; }

            const float4 p = P0l[idx];                   // {x0, 1/w, y0, h}
            const float2 q = P1l[idx];                   // {d0, d0+d1-2s}
            const float theta = (z - p.x) * p.y;
            const float t1m = theta * (1.0f - theta);
            const float s = p.w * p.y;                   // h/w
            const float den = fmaf(q.y, t1m, s);
            const float num = fmaf(s * theta, theta, q.x * t1m);
            res = fmaf(p.w, __fdividef(num, den), p.z);
        } else {
            res = z;
        }
        out[(long)r * D + d] = tv * fmaf(res, scale, bi);
    }
}

extern "C" void kernel_launch(void* const* d_in, const int* in_sizes, int n_in,
                              void* d_out, int out_size) {
    const float* u         = (const float*)d_in[0];
    const float* tau       = (const float*)d_in[1];
    const float* log_scale = (const float*)d_in[2];
    const float* bias      = (const float*)d_in[3];
    const float* raw_w     = (const float*)d_in[4];
    const float* raw_h     = (const float*)d_in[5];
    const float* raw_s     = (const float*)d_in[6];
    float* out = (float*)d_out;

    const int D = in_sizes[2];
    const int B = in_sizes[0] / D;

    spline_preproc_kernel<<<D, K64>>>(raw_w, raw_h, raw_s, log_scale);

    // Single-wave grid: smem ~32.6KB/block -> 6 blocks/SM -> 888 concurrent on 148 SMs.
    // 64 x 13 = 832 blocks, persistent row loop covers all of B.
    dim3 grid(D / DTILE, 13);
    rqs_main_kernel<<<grid, TPB>>>(u, tau, bias, out, B, D);
}